// round 16
// baseline (speedup 1.0000x reference)
#include <cuda_runtime.h>
#include <cuda_fp16.h>
#include <math.h>
#include <stdint.h>

#define BSZ  4
#define TLEN 2048
#define DIN_ 512
#define DM_  1024
#define DO_  1024
#define LNUM 2
#define DS_  16
#define DC_  4
#define DI_  2048
#define DTR_ 64
#define MROWS (BSZ*TLEN)
#define DBCW  (DTR_ + 2*DS_)      // 96

__device__ float g_x   [(size_t)MROWS*DM_];
__device__ float g_xz  [(size_t)MROWS*2*DI_];
__device__ float g_u   [(size_t)MROWS*DI_];
__device__ float g_dbc [(size_t)MROWS*DBCW];
__device__ float g_delta[(size_t)MROWS*DI_];
__device__ float g_ob  [(size_t)MROWS*DO_];
__device__ int   g_len [BSZ];
__device__ __half g_ah[(size_t)MROWS*2048];    // activation fp16 staging
__device__ __half g_wh[(size_t)4096*2048];     // weight fp16 staging
__device__ __half g_dh[(size_t)MROWS*DBCW];    // dbc fp16 (dt GEMM A)

__device__ __forceinline__ uint32_t smem_u32(const void* p) {
    uint32_t a;
    asm("{ .reg .u64 t; cvta.to.shared.u64 t, %1; cvt.u32.u64 %0, t; }" : "=r"(a) : "l"(p));
    return a;
}
__device__ __forceinline__ void cp_async16(uint32_t d, const void* g, int sz) {
    asm volatile("cp.async.cg.shared.global [%0], [%1], 16, %2;"
                 :: "r"(d), "l"(g), "r"(sz) : "memory");
}
__device__ __forceinline__ void ldm4(uint32_t* r, uint32_t addr) {
    asm volatile("ldmatrix.sync.aligned.m8n8.x4.shared.b16 {%0,%1,%2,%3}, [%4];"
        : "=r"(r[0]), "=r"(r[1]), "=r"(r[2]), "=r"(r[3]) : "r"(addr));
}
__device__ __forceinline__ void mma16816(float* d, const uint32_t* a,
                                         uint32_t b0, uint32_t b1) {
    asm volatile("mma.sync.aligned.m16n8k16.row.col.f32.f16.f16.f32 "
        "{%0,%1,%2,%3}, {%4,%5,%6,%7}, {%8,%9}, {%0,%1,%2,%3};"
        : "+f"(d[0]), "+f"(d[1]), "+f"(d[2]), "+f"(d[3])
        : "r"(a[0]), "r"(a[1]), "r"(a[2]), "r"(a[3]), "r"(b0), "r"(b1));
}

__global__ void convert_h(const float* __restrict__ src,
                          __half* __restrict__ dst, size_t n4)
{
    size_t i = (size_t)blockIdx.x * blockDim.x + threadIdx.x;
    if (i >= n4) return;
    float4 v = ((const float4*)src)[i];
    ((__half2*)dst)[i*2]   = __float22half2_rn(make_float2(v.x, v.y));
    ((__half2*)dst)[i*2+1] = __float22half2_rn(make_float2(v.z, v.w));
}

#define STAGES 3
#define STAGE_BYTES 32768u
#define GTC_SMEM (STAGES * STAGE_BYTES)

// C = A(MxK, lda) * W(NxK, ldb)^T
// flags: bit0 accumulate, bit1 softplus, bit2 skip masked M-tiles.
// hout!=null -> also write fp16 C copy.
__global__ __launch_bounds__(256, 2)
void gemm_mma(const __half* __restrict__ A, int lda,
              const __half* __restrict__ W, int ldb,
              const float* __restrict__ bias,
              float* __restrict__ C, int ldc,
              __half* __restrict__ hout, int hld,
              int N, int K, int nch, int flags)
{
    const int bm = blockIdx.y << 7, bn = blockIdx.x << 7;
    if (flags & 4) {
        if ((bm & (TLEN - 1)) >= g_len[bm >> 11]) return;   // whole tile masked
    }
    extern __shared__ char smem[];
    const uint32_t sbase = smem_u32(smem);
    const int tid  = threadIdx.x;
    const int lane = tid & 31, wid = tid >> 5;
    const int warpM = (wid & 1) << 6;
    const int warpN = (wid >> 1) << 5;

    float acc[4][4][4];
#pragma unroll
    for (int i = 0; i < 4; i++)
#pragma unroll
        for (int j = 0; j < 4; j++)
#pragma unroll
            for (int k = 0; k < 4; k++) acc[i][j][k] = 0.f;

    const int r_a   = (lane & 7) + ((lane >> 3) & 1) * 8;
    const int cpart = lane >> 4;
    const int rx    = lane & 7;
    uint32_t a_row[4], b_row[2], csel[4];
#pragma unroll
    for (int mi = 0; mi < 4; mi++) a_row[mi] = (uint32_t)(warpM + mi*16 + r_a) * 128u;
#pragma unroll
    for (int bi = 0; bi < 2; bi++) b_row[bi] = 16384u + (uint32_t)(warpN + bi*16 + r_a) * 128u;
#pragma unroll
    for (int ks = 0; ks < 4; ks++) csel[ks] = (uint32_t)(((2*ks + cpart) ^ rx) << 4);

    const int ldch  = tid & 7;
    const int ldrow = tid >> 3;
    const uint32_t swz = (uint32_t)((ldch ^ (ldrow & 7)) << 4);

    auto load_stage = [&](int c, int stg) {
        const uint32_t sbs = sbase + (uint32_t)stg * STAGE_BYTES;
        const int kk = (c << 6) + (ldch << 3);
        const int aok = (kk < K) ? 16 : 0;
#pragma unroll
        for (int i = 0; i < 4; i++) {
            const int row = ldrow + (i << 5);
            const uint32_t off = (uint32_t)row * 128u + swz;
            cp_async16(sbs + off, A + (size_t)(bm + row) * lda + kk, aok);
            const int brow = bn + row;
            const int bok = (kk < K && brow < N) ? 16 : 0;
            cp_async16(sbs + 16384u + off, W + (size_t)(bok ? brow : 0) * ldb + kk, bok);
        }
        asm volatile("cp.async.commit_group;" ::: "memory");
    };

    for (int s = 0; s < STAGES - 1 && s < nch; s++) load_stage(s, s);

    for (int c = 0; c < nch; c++) {
        asm volatile("cp.async.wait_group %0;" :: "n"(STAGES - 2) : "memory");
        __syncthreads();
        const uint32_t sA = sbase + (uint32_t)(c % STAGES) * STAGE_BYTES;
        // issue next stage's loads BEFORE compute so cp.async overlaps MMA
        if (c + STAGES - 1 < nch) load_stage(c + STAGES - 1, (c + STAGES - 1) % STAGES);
#pragma unroll
        for (int ks = 0; ks < 4; ks++) {
            uint32_t af[4][4], bf[2][4];
#pragma unroll
            for (int mi = 0; mi < 4; mi++) ldm4(af[mi], sA + a_row[mi] + csel[ks]);
#pragma unroll
            for (int bi = 0; bi < 2; bi++) ldm4(bf[bi], sA + b_row[bi] + csel[ks]);
#pragma unroll
            for (int mi = 0; mi < 4; mi++) {
#pragma unroll
                for (int ni = 0; ni < 4; ni++) {
                    const int bi = ni >> 1, sel = ni & 1;
                    mma16816(acc[mi][ni], af[mi], bf[bi][sel], bf[bi][sel + 2]);
                }
            }
        }
    }

    const int g = lane >> 2;
    const int ncol = (lane & 3) * 2;
#pragma unroll
    for (int mi = 0; mi < 4; mi++) {
        const int m0 = bm + warpM + mi*16 + g;
#pragma unroll
        for (int ni = 0; ni < 4; ni++) {
            const int n = bn + warpN + ni*8 + ncol;
            if (n >= N) continue;
            float v[4] = {acc[mi][ni][0], acc[mi][ni][1], acc[mi][ni][2], acc[mi][ni][3]};
            if (bias) {
                float b0 = bias[n], b1 = bias[n+1];
                v[0] += b0; v[1] += b1; v[2] += b0; v[3] += b1;
            }
            if (flags & 2) {
#pragma unroll
                for (int k = 0; k < 4; k++)
                    v[k] = (v[k] > 20.f) ? v[k] : log1pf(expf(v[k]));
            }
            float* p0 = C + (size_t)m0 * ldc + n;
            float* p1 = C + (size_t)(m0 + 8) * ldc + n;
            if (flags & 1) {
                float2 o0 = *(const float2*)p0, o1 = *(const float2*)p1;
                v[0] += o0.x; v[1] += o0.y; v[2] += o1.x; v[3] += o1.y;
            }
            *(float2*)p0 = make_float2(v[0], v[1]);
            *(float2*)p1 = make_float2(v[2], v[3]);
            if (hout) {
                *(__half2*)(hout + (size_t)m0 * hld + n) =
                    __float22half2_rn(make_float2(v[0], v[1]));
                *(__half2*)(hout + (size_t)(m0 + 8) * hld + n) =
                    __float22half2_rn(make_float2(v[2], v[3]));
            }
        }
    }
}

__global__ void detect_mask_kernel(const unsigned char* __restrict__ mb) {
    __shared__ int s_weird, s_off, s_cnt[BSZ];
    int tid = threadIdx.x;
    if (tid == 0) { s_weird = 0; s_off = 0; }
    if (tid < BSZ) s_cnt[tid] = 0;
    __syncthreads();
    for (int i = tid; i < BSZ*TLEN; i += blockDim.x) {
        unsigned char c = mb[i];
        if (c > 1) s_weird = 1;
        else if (c && (i & 3)) s_off = 1;
    }
    __syncthreads();
    int mode = s_weird ? 2 : (s_off ? 0 : 1);
    for (int i = tid; i < BSZ*TLEN; i += blockDim.x) {
        int b = i / TLEN;
        int v;
        if (mode == 0)      v = mb[i];
        else if (mode == 1) v = ((const int*)mb)[i];
        else                v = (((const float*)mb)[i] != 0.0f);
        if (!v) atomicAdd(&s_cnt[b], 1);
    }
    __syncthreads();
    if (tid < BSZ) g_len[tid] = s_cnt[tid];
}

// layernorm, fp16 direct output; masked rows skipped
__global__ void layernorm_h_kernel(const float* __restrict__ x,
                                   const float* __restrict__ w,
                                   const float* __restrict__ bb,
                                   __half* __restrict__ y)
{
    int row = blockIdx.x, tid = threadIdx.x;
    if ((row & (TLEN - 1)) >= g_len[row >> 11]) return;
    const float* xr = x + (size_t)row * DM_;
    float4 v = *(const float4*)(xr + tid * 4);
    float s  = v.x + v.y + v.z + v.w;
    float ss = v.x*v.x + v.y*v.y + v.z*v.z + v.w*v.w;
#pragma unroll
    for (int o = 16; o > 0; o >>= 1) {
        s  += __shfl_xor_sync(0xffffffffu, s, o);
        ss += __shfl_xor_sync(0xffffffffu, ss, o);
    }
    __shared__ float rs_[8], rss[8];
    int wid = tid >> 5, lane = tid & 31;
    if (lane == 0) { rs_[wid] = s; rss[wid] = ss; }
    __syncthreads();
    if (tid == 0) {
        float ts = 0.f, tss = 0.f;
        for (int i = 0; i < 8; i++) { ts += rs_[i]; tss += rss[i]; }
        rs_[0] = ts; rss[0] = tss;
    }
    __syncthreads();
    float mu  = rs_[0] * (1.f / DM_);
    float var = rss[0] * (1.f / DM_) - mu * mu;
    float inv = rsqrtf(var + 1e-5f);
    float4 wv = *(const float4*)(w + tid * 4);
    float4 bv = *(const float4*)(bb + tid * 4);
    float o0 = (v.x - mu) * inv * wv.x + bv.x;
    float o1 = (v.y - mu) * inv * wv.y + bv.y;
    float o2 = (v.z - mu) * inv * wv.z + bv.z;
    float o3 = (v.w - mu) * inv * wv.w + bv.w;
    __half* yr = y + (size_t)row * DM_ + tid * 4;
    *(__half2*)(yr)     = __float22half2_rn(make_float2(o0, o1));
    *(__half2*)(yr + 2) = __float22half2_rn(make_float2(o2, o3));
}

// causal depthwise conv + bias + silu; masked rows skipped
__global__ void conv_silu_kernel(const float* __restrict__ cw,
                                 const float* __restrict__ cb)
{
    size_t idx = (size_t)blockIdx.x * blockDim.x + threadIdx.x;
    int d = (int)(idx % DI_);
    size_t r = idx / DI_;
    int t = (int)(r % TLEN);
    if (t >= g_len[(int)(r >> 11)]) return;
    const size_t base = r * (size_t)(2 * DI_) + d;
    float acc = cb[d];
#pragma unroll
    for (int j = 0; j < DC_; j++) {
        int tt = t - (DC_ - 1) + j;
        if (tt >= 0)
            acc += g_xz[base + (size_t)(j - (DC_ - 1)) * (2 * DI_)] * cw[d * DC_ + j];
    }
    float sg = 1.f / (1.f + __expf(-acc));
    float u = acc * sg;
    g_u[r * DI_ + d] = u;
    g_ah[r * DI_ + d] = __float2half(u);
}

// selective scan + fused silu(z) gate, fp16 out, masked tail skipped.
// Loads batched 8 timesteps ahead (40 floats in regs, ~70 total -> no spill).
#define SB 8
__global__ void scan_kernel(const float* __restrict__ Alog,
                            const float* __restrict__ Dp)
{
    int gw   = (int)((blockIdx.x * blockDim.x + threadIdx.x) >> 5);
    int lane = threadIdx.x & 31;
    int b  = gw >> 10;
    int dp = gw & 1023;
    int s  = lane & 15;
    int half = lane >> 4;
    int d = dp * 2 + half;

    const float Av = -expf(Alog[d * DS_ + s]);
    const float Dv = Dp[d];
    float h = 0.f;
    int len = g_len[b];
    if (len < 1) len = 1;
    if (len > TLEN) len = TLEN;
    const int lenB = len & ~(SB - 1);
    const size_t brow0 = (size_t)b * TLEN;

    const float* __restrict__ pd = g_delta + brow0 * DI_ + d;
    const float* __restrict__ pu = g_u     + brow0 * DI_ + d;
    const float* __restrict__ pB = g_dbc   + brow0 * DBCW + DTR_ + s;
    const float* __restrict__ pz = g_xz    + brow0 * (size_t)(2*DI_) + DI_ + d;
    __half*      __restrict__ py = g_ah    + brow0 * DI_ + d;

    int t = 0;
    for (; t < lenB; t += SB) {
        float dl[SB], uu[SB], Bv[SB], Cv[SB], zz[SB];
#pragma unroll
        for (int i = 0; i < SB; i++) {
            const size_t ro = (size_t)(t + i);
            dl[i] = pd[ro * DI_];
            uu[i] = pu[ro * DI_];
            Bv[i] = pB[ro * DBCW];
            Cv[i] = pB[ro * DBCW + DS_];
            if (s == 0) zz[i] = pz[ro * (size_t)(2*DI_)];
        }
#pragma unroll
        for (int i = 0; i < SB; i++) {
            float e = __expf(dl[i] * Av);
            h = h * e + (dl[i] * uu[i]) * Bv[i];
            float p = h * Cv[i];
            p += __shfl_xor_sync(0xffffffffu, p, 1);
            p += __shfl_xor_sync(0xffffffffu, p, 2);
            p += __shfl_xor_sync(0xffffffffu, p, 4);
            p += __shfl_xor_sync(0xffffffffu, p, 8);
            if (s == 0) {
                float sg = zz[i] / (1.f + __expf(-zz[i]));
                py[(size_t)(t + i) * DI_] = __float2half((p + uu[i] * Dv) * sg);
            }
        }
    }
    for (; t < len; t++) {
        const size_t ro = (size_t)t;
        float dl = pd[ro * DI_], uu = pu[ro * DI_];
        float Bv = pB[ro * DBCW], Cv = pB[ro * DBCW + DS_];
        float e = __expf(dl * Av);
        h = h * e + (dl * uu) * Bv;
        float p = h * Cv;
        p += __shfl_xor_sync(0xffffffffu, p, 1);
        p += __shfl_xor_sync(0xffffffffu, p, 2);
        p += __shfl_xor_sync(0xffffffffu, p, 4);
        p += __shfl_xor_sync(0xffffffffu, p, 8);
        if (s == 0) {
            float z = pz[ro * (size_t)(2*DI_)];
            float sg = z / (1.f + __expf(-z));
            py[ro * DI_] = __float2half((p + uu * Dv) * sg);
        }
    }
}

__global__ void mean_kernel(float* __restrict__ out)
{
    int b = blockIdx.y;
    int o = blockIdx.x * blockDim.x + threadIdx.x;
    int len = g_len[b];
    if (len < 1) len = 1;
    const float* p = g_ob + ((size_t)b * TLEN) * DO_ + o;
    float sum = 0.f;
    int t = 0;
    const int len4 = len & ~3;
    for (; t < len4; t += 4) {
        float v0 = p[(size_t)(t+0) * DO_];
        float v1 = p[(size_t)(t+1) * DO_];
        float v2 = p[(size_t)(t+2) * DO_];
        float v3 = p[(size_t)(t+3) * DO_];
        sum += (v0 + v1) + (v2 + v3);
    }
    for (; t < len; t++) sum += p[(size_t)t * DO_];
    out[b * DO_ + o] = sum / (float)len;
}

static void launch_gemm(const __half* A, int lda, const __half* W, int ldb,
                        const float* bias, float* C, int ldc,
                        __half* hout, int hld,
                        int M, int N, int K, int flags)
{
    int nch = (K + 63) / 64;
    if (nch < 2) nch = 2;
    dim3 grid((N + 127) / 128, M / 128);
    gemm_mma<<<grid, 256, GTC_SMEM>>>(A, lda, W, ldb, bias, C, ldc,
                                      hout, hld, N, K, nch, flags);
}
static void conv_w(const float* W, __half* wh, size_t n) {
    convert_h<<<(unsigned)((n/4 + 255) / 256), 256>>>(W, wh, n/4);
}

extern "C" void kernel_launch(void* const* d_in, const int* in_sizes, int n_in,
                              void* d_out, int out_size)
{
    const float* features  = (const float*)d_in[0];
    const void*  mask      = d_in[1];
    const float* inp_w     = (const float*)d_in[2];
    const float* inp_b     = (const float*)d_in[3];
    const float* norm_w    = (const float*)d_in[4];
    const float* norm_b    = (const float*)d_in[5];
    const float* in_proj_w = (const float*)d_in[6];
    const float* conv_w_   = (const float*)d_in[7];
    const float* conv_b    = (const float*)d_in[8];
    const float* x_proj_w  = (const float*)d_in[9];
    const float* dt_proj_w = (const float*)d_in[10];
    const float* dt_proj_b = (const float*)d_in[11];
    const float* A_log     = (const float*)d_in[12];
    const float* Dskip     = (const float*)d_in[13];
    const float* mout_w    = (const float*)d_in[14];
    const float* out_w     = (const float*)d_in[15];
    const float* out_b     = (const float*)d_in[16];
    float* out = (float*)d_out;

    cudaFuncSetAttribute(gemm_mma, cudaFuncAttributeMaxDynamicSharedMemorySize, GTC_SMEM);

    float *px, *pxz, *pu, *pdbc, *pdelta, *pob;
    __half *pah, *pwh, *pdh;
    cudaGetSymbolAddress((void**)&px,     g_x);
    cudaGetSymbolAddress((void**)&pxz,    g_xz);
    cudaGetSymbolAddress((void**)&pu,     g_u);
    cudaGetSymbolAddress((void**)&pdbc,   g_dbc);
    cudaGetSymbolAddress((void**)&pdelta, g_delta);
    cudaGetSymbolAddress((void**)&pob,    g_ob);
    cudaGetSymbolAddress((void**)&pah,    g_ah);
    cudaGetSymbolAddress((void**)&pwh,    g_wh);
    cudaGetSymbolAddress((void**)&pdh,    g_dh);

    detect_mask_kernel<<<1, 256>>>((const unsigned char*)mask);

    // x = features @ inp_w^T + inp_b   (masked tiles skipped)
    convert_h<<<(unsigned)(((size_t)MROWS*DIN_/4 + 255)/256), 256>>>(
        features, pah, (size_t)MROWS*DIN_/4);
    conv_w(inp_w, pwh, (size_t)DM_*DIN_);
    launch_gemm(pah, DIN_, pwh, DIN_, inp_b, px, DM_, nullptr, 0,
                MROWS, DM_, DIN_, 4);

    for (int l = 0; l < LNUM; l++) {
        // xn (fp16 direct, masked rows skipped)
        layernorm_h_kernel<<<MROWS, 256>>>(px, norm_w + l*DM_, norm_b + l*DM_, pah);

        // xz = xn @ in_proj_w^T
        conv_w(in_proj_w + (size_t)l*2*DI_*DM_, pwh, (size_t)2*DI_*DM_);
        launch_gemm(pah, DM_, pwh, DM_, nullptr, pxz, 2*DI_, nullptr, 0,
                    MROWS, 2*DI_, DM_, 4);

        // u = silu(conv(xi)+b): fp32 + fp16 dual write, masked rows skipped
        conv_silu_kernel<<<(unsigned)((MROWS*(size_t)DI_)/256), 256>>>(
            conv_w_ + (size_t)l*DI_*DC_, conv_b + l*DI_);

        // dbc = u @ x_proj_w^T  (fp32 + fp16 dual write)
        conv_w(x_proj_w + (size_t)l*DBCW*DI_, pwh, (size_t)DBCW*DI_);
        launch_gemm(pah, DI_, pwh, DI_, nullptr, pdbc, DBCW, pdh, DBCW,
                    MROWS, DBCW, DI_, 4);

        // delta = softplus(dt @ dt_proj_w^T + dt_proj_b)
        conv_w(dt_proj_w + (size_t)l*DI_*DTR_, pwh, (size_t)DI_*DTR_);
        launch_gemm(pdh, DBCW, pwh, DTR_, dt_proj_b + l*DI_, pdelta, DI_,
                    nullptr, 0, MROWS, DI_, DTR_, 2 | 4);

        // selective scan + fused gate, batched loads (SB=8), tail skipped
        scan_kernel<<<512, 256>>>(A_log + (size_t)l*DI_*DS_, Dskip + l*DI_);

        // x += y_gated @ mout_w^T
        conv_w(mout_w + (size_t)l*DM_*DI_, pwh, (size_t)DM_*DI_);
        launch_gemm(pah, DI_, pwh, DI_, nullptr, px, DM_, nullptr, 0,
                    MROWS, DM_, DI_, 1 | 4);
    }

    // ob = x @ out_w^T + out_b
    convert_h<<<(unsigned)(((size_t)MROWS*DM_/4 + 255)/256), 256>>>(
        px, pah, (size_t)MROWS*DM_/4);
    conv_w(out_w, pwh, (size_t)DO_*DM_);
    launch_gemm(pah, DM_, pwh, DM_, out_b, pob, DO_, nullptr, 0,
                MROWS, DO_, DM_, 4);

    mean_kernel<<<dim3(DO_/256, BSZ), 256>>>(out);
}

// round 17
// speedup vs baseline: 1.7519x; 1.7519x over previous
#include <cuda_runtime.h>
#include <cuda_fp16.h>
#include <math.h>
#include <stdint.h>

#define BSZ  4
#define TLEN 2048
#define DIN_ 512
#define DM_  1024
#define DO_  1024
#define LNUM 2
#define DS_  16
#define DC_  4
#define DI_  2048
#define DTR_ 64
#define MROWS (BSZ*TLEN)
#define DBCW  (DTR_ + 2*DS_)      // 96

__device__ float g_x   [(size_t)MROWS*DM_];
__device__ float g_xz  [(size_t)MROWS*2*DI_];
__device__ float g_u   [(size_t)MROWS*DI_];
__device__ float g_dbc [(size_t)MROWS*DBCW];
__device__ float g_delta[(size_t)MROWS*DI_];   // also mean partial scratch
__device__ float g_ob  [(size_t)MROWS*DO_];
__device__ int   g_len [BSZ];
__device__ __half g_ah[(size_t)MROWS*2048];    // activation fp16 staging
__device__ __half g_wh[(size_t)4096*2048];     // weight fp16 staging
__device__ __half g_dh[(size_t)MROWS*DBCW];    // dbc fp16 (dt GEMM A)

__device__ __forceinline__ uint32_t smem_u32(const void* p) {
    uint32_t a;
    asm("{ .reg .u64 t; cvta.to.shared.u64 t, %1; cvt.u32.u64 %0, t; }" : "=r"(a) : "l"(p));
    return a;
}
__device__ __forceinline__ void cp_async16(uint32_t d, const void* g, int sz) {
    asm volatile("cp.async.cg.shared.global [%0], [%1], 16, %2;"
                 :: "r"(d), "l"(g), "r"(sz) : "memory");
}
__device__ __forceinline__ void ldm4(uint32_t* r, uint32_t addr) {
    asm volatile("ldmatrix.sync.aligned.m8n8.x4.shared.b16 {%0,%1,%2,%3}, [%4];"
        : "=r"(r[0]), "=r"(r[1]), "=r"(r[2]), "=r"(r[3]) : "r"(addr));
}
__device__ __forceinline__ void mma16816(float* d, const uint32_t* a,
                                         uint32_t b0, uint32_t b1) {
    asm volatile("mma.sync.aligned.m16n8k16.row.col.f32.f16.f16.f32 "
        "{%0,%1,%2,%3}, {%4,%5,%6,%7}, {%8,%9}, {%0,%1,%2,%3};"
        : "+f"(d[0]), "+f"(d[1]), "+f"(d[2]), "+f"(d[3])
        : "r"(a[0]), "r"(a[1]), "r"(a[2]), "r"(a[3]), "r"(b0), "r"(b1));
}

__global__ void convert_h(const float* __restrict__ src,
                          __half* __restrict__ dst, size_t n4)
{
    size_t i = (size_t)blockIdx.x * blockDim.x + threadIdx.x;
    if (i >= n4) return;
    float4 v = ((const float4*)src)[i];
    ((__half2*)dst)[i*2]   = __float22half2_rn(make_float2(v.x, v.y));
    ((__half2*)dst)[i*2+1] = __float22half2_rn(make_float2(v.z, v.w));
}

#define STAGES 3
#define STAGE_BYTES 32768u
#define GTC_SMEM (STAGES * STAGE_BYTES)

// C = A(MxK, lda) * W(NxK, ldb)^T
// flags: bit0 accumulate, bit1 softplus, bit2 skip masked M-tiles.
// hout!=null -> also write fp16 C copy.
__global__ __launch_bounds__(256, 2)
void gemm_mma(const __half* __restrict__ A, int lda,
              const __half* __restrict__ W, int ldb,
              const float* __restrict__ bias,
              float* __restrict__ C, int ldc,
              __half* __restrict__ hout, int hld,
              int N, int K, int nch, int flags)
{
    const int bm = blockIdx.y << 7, bn = blockIdx.x << 7;
    if (flags & 4) {
        if ((bm & (TLEN - 1)) >= g_len[bm >> 11]) return;   // whole tile masked
    }
    extern __shared__ char smem[];
    const uint32_t sbase = smem_u32(smem);
    const int tid  = threadIdx.x;
    const int lane = tid & 31, wid = tid >> 5;
    const int warpM = (wid & 1) << 6;
    const int warpN = (wid >> 1) << 5;

    float acc[4][4][4];
#pragma unroll
    for (int i = 0; i < 4; i++)
#pragma unroll
        for (int j = 0; j < 4; j++)
#pragma unroll
            for (int k = 0; k < 4; k++) acc[i][j][k] = 0.f;

    const int r_a   = (lane & 7) + ((lane >> 3) & 1) * 8;
    const int cpart = lane >> 4;
    const int rx    = lane & 7;
    uint32_t a_row[4], b_row[2], csel[4];
#pragma unroll
    for (int mi = 0; mi < 4; mi++) a_row[mi] = (uint32_t)(warpM + mi*16 + r_a) * 128u;
#pragma unroll
    for (int bi = 0; bi < 2; bi++) b_row[bi] = 16384u + (uint32_t)(warpN + bi*16 + r_a) * 128u;
#pragma unroll
    for (int ks = 0; ks < 4; ks++) csel[ks] = (uint32_t)(((2*ks + cpart) ^ rx) << 4);

    const int ldch  = tid & 7;
    const int ldrow = tid >> 3;
    const uint32_t swz = (uint32_t)((ldch ^ (ldrow & 7)) << 4);

    auto load_stage = [&](int c, int stg) {
        const uint32_t sbs = sbase + (uint32_t)stg * STAGE_BYTES;
        const int kk = (c << 6) + (ldch << 3);
        const int aok = (kk < K) ? 16 : 0;
#pragma unroll
        for (int i = 0; i < 4; i++) {
            const int row = ldrow + (i << 5);
            const uint32_t off = (uint32_t)row * 128u + swz;
            cp_async16(sbs + off, A + (size_t)(bm + row) * lda + kk, aok);
            const int brow = bn + row;
            const int bok = (kk < K && brow < N) ? 16 : 0;
            cp_async16(sbs + 16384u + off, W + (size_t)(bok ? brow : 0) * ldb + kk, bok);
        }
        asm volatile("cp.async.commit_group;" ::: "memory");
    };

    for (int s = 0; s < STAGES - 1 && s < nch; s++) load_stage(s, s);

    for (int c = 0; c < nch; c++) {
        asm volatile("cp.async.wait_group %0;" :: "n"(STAGES - 2) : "memory");
        __syncthreads();
        const uint32_t sA = sbase + (uint32_t)(c % STAGES) * STAGE_BYTES;
#pragma unroll
        for (int ks = 0; ks < 4; ks++) {
            uint32_t af[4][4], bf[2][4];
#pragma unroll
            for (int mi = 0; mi < 4; mi++) ldm4(af[mi], sA + a_row[mi] + csel[ks]);
#pragma unroll
            for (int bi = 0; bi < 2; bi++) ldm4(bf[bi], sA + b_row[bi] + csel[ks]);
#pragma unroll
            for (int mi = 0; mi < 4; mi++) {
#pragma unroll
                for (int ni = 0; ni < 4; ni++) {
                    const int bi = ni >> 1, sel = ni & 1;
                    mma16816(acc[mi][ni], af[mi], bf[bi][sel], bf[bi][sel + 2]);
                }
            }
        }
        if (c + STAGES - 1 < nch) load_stage(c + STAGES - 1, (c + STAGES - 1) % STAGES);
    }

    const int g = lane >> 2;
    const int ncol = (lane & 3) * 2;
#pragma unroll
    for (int mi = 0; mi < 4; mi++) {
        const int m0 = bm + warpM + mi*16 + g;
#pragma unroll
        for (int ni = 0; ni < 4; ni++) {
            const int n = bn + warpN + ni*8 + ncol;
            if (n >= N) continue;
            float v[4] = {acc[mi][ni][0], acc[mi][ni][1], acc[mi][ni][2], acc[mi][ni][3]};
            if (bias) {
                float b0 = bias[n], b1 = bias[n+1];
                v[0] += b0; v[1] += b1; v[2] += b0; v[3] += b1;
            }
            if (flags & 2) {
#pragma unroll
                for (int k = 0; k < 4; k++)
                    v[k] = (v[k] > 20.f) ? v[k] : log1pf(expf(v[k]));
            }
            float* p0 = C + (size_t)m0 * ldc + n;
            float* p1 = C + (size_t)(m0 + 8) * ldc + n;
            if (flags & 1) {
                float2 o0 = *(const float2*)p0, o1 = *(const float2*)p1;
                v[0] += o0.x; v[1] += o0.y; v[2] += o1.x; v[3] += o1.y;
            }
            *(float2*)p0 = make_float2(v[0], v[1]);
            *(float2*)p1 = make_float2(v[2], v[3]);
            if (hout) {
                *(__half2*)(hout + (size_t)m0 * hld + n) =
                    __float22half2_rn(make_float2(v[0], v[1]));
                *(__half2*)(hout + (size_t)(m0 + 8) * hld + n) =
                    __float22half2_rn(make_float2(v[2], v[3]));
            }
        }
    }
}

__global__ void detect_mask_kernel(const unsigned char* __restrict__ mb) {
    __shared__ int s_weird, s_off, s_cnt[BSZ];
    int tid = threadIdx.x;
    if (tid == 0) { s_weird = 0; s_off = 0; }
    if (tid < BSZ) s_cnt[tid] = 0;
    __syncthreads();
    for (int i = tid; i < BSZ*TLEN; i += blockDim.x) {
        unsigned char c = mb[i];
        if (c > 1) s_weird = 1;
        else if (c && (i & 3)) s_off = 1;
    }
    __syncthreads();
    int mode = s_weird ? 2 : (s_off ? 0 : 1);
    for (int i = tid; i < BSZ*TLEN; i += blockDim.x) {
        int b = i / TLEN;
        int v;
        if (mode == 0)      v = mb[i];
        else if (mode == 1) v = ((const int*)mb)[i];
        else                v = (((const float*)mb)[i] != 0.0f);
        if (!v) atomicAdd(&s_cnt[b], 1);
    }
    __syncthreads();
    if (tid < BSZ) g_len[tid] = s_cnt[tid];
}

// layernorm, fp16 direct output; masked rows skipped
__global__ void layernorm_h_kernel(const float* __restrict__ x,
                                   const float* __restrict__ w,
                                   const float* __restrict__ bb,
                                   __half* __restrict__ y)
{
    int row = blockIdx.x, tid = threadIdx.x;
    if ((row & (TLEN - 1)) >= g_len[row >> 11]) return;
    const float* xr = x + (size_t)row * DM_;
    float4 v = *(const float4*)(xr + tid * 4);
    float s  = v.x + v.y + v.z + v.w;
    float ss = v.x*v.x + v.y*v.y + v.z*v.z + v.w*v.w;
#pragma unroll
    for (int o = 16; o > 0; o >>= 1) {
        s  += __shfl_xor_sync(0xffffffffu, s, o);
        ss += __shfl_xor_sync(0xffffffffu, ss, o);
    }
    __shared__ float rs_[8], rss[8];
    int wid = tid >> 5, lane = tid & 31;
    if (lane == 0) { rs_[wid] = s; rss[wid] = ss; }
    __syncthreads();
    if (tid == 0) {
        float ts = 0.f, tss = 0.f;
        for (int i = 0; i < 8; i++) { ts += rs_[i]; tss += rss[i]; }
        rs_[0] = ts; rss[0] = tss;
    }
    __syncthreads();
    float mu  = rs_[0] * (1.f / DM_);
    float var = rss[0] * (1.f / DM_) - mu * mu;
    float inv = rsqrtf(var + 1e-5f);
    float4 wv = *(const float4*)(w + tid * 4);
    float4 bv = *(const float4*)(bb + tid * 4);
    float o0 = (v.x - mu) * inv * wv.x + bv.x;
    float o1 = (v.y - mu) * inv * wv.y + bv.y;
    float o2 = (v.z - mu) * inv * wv.z + bv.z;
    float o3 = (v.w - mu) * inv * wv.w + bv.w;
    __half* yr = y + (size_t)row * DM_ + tid * 4;
    *(__half2*)(yr)     = __float22half2_rn(make_float2(o0, o1));
    *(__half2*)(yr + 2) = __float22half2_rn(make_float2(o2, o3));
}

// causal depthwise conv + bias + silu; masked rows skipped
__global__ void conv_silu_kernel(const float* __restrict__ cw,
                                 const float* __restrict__ cb)
{
    size_t idx = (size_t)blockIdx.x * blockDim.x + threadIdx.x;
    int d = (int)(idx % DI_);
    size_t r = idx / DI_;
    int t = (int)(r % TLEN);
    if (t >= g_len[(int)(r >> 11)]) return;
    const size_t base = r * (size_t)(2 * DI_) + d;
    float acc = cb[d];
#pragma unroll
    for (int j = 0; j < DC_; j++) {
        int tt = t - (DC_ - 1) + j;
        if (tt >= 0)
            acc += g_xz[base + (size_t)(j - (DC_ - 1)) * (2 * DI_)] * cw[d * DC_ + j];
    }
    float sg = 1.f / (1.f + __expf(-acc));
    float u = acc * sg;
    g_u[r * DI_ + d] = u;
    g_ah[r * DI_ + d] = __float2half(u);
}

// selective scan + fused silu(z) gate, fp16 out, masked tail skipped.
// Loads batched 4 timesteps ahead (verified win; 20 floats in regs).
#define SB 4
__global__ void scan_kernel(const float* __restrict__ Alog,
                            const float* __restrict__ Dp)
{
    int gw   = (int)((blockIdx.x * blockDim.x + threadIdx.x) >> 5);
    int lane = threadIdx.x & 31;
    int b  = gw >> 10;
    int dp = gw & 1023;
    int s  = lane & 15;
    int half = lane >> 4;
    int d = dp * 2 + half;

    const float Av = -expf(Alog[d * DS_ + s]);
    const float Dv = Dp[d];
    float h = 0.f;
    int len = g_len[b];
    if (len < 1) len = 1;
    if (len > TLEN) len = TLEN;
    const int lenB = len & ~(SB - 1);
    const size_t brow0 = (size_t)b * TLEN;

    const float* __restrict__ pd = g_delta + brow0 * DI_ + d;
    const float* __restrict__ pu = g_u     + brow0 * DI_ + d;
    const float* __restrict__ pB = g_dbc   + brow0 * DBCW + DTR_ + s;
    const float* __restrict__ pz = g_xz    + brow0 * (size_t)(2*DI_) + DI_ + d;
    __half*      __restrict__ py = g_ah    + brow0 * DI_ + d;

    int t = 0;
    for (; t < lenB; t += SB) {
        float dl[SB], uu[SB], Bv[SB], Cv[SB], zz[SB];
#pragma unroll
        for (int i = 0; i < SB; i++) {
            const size_t ro = (size_t)(t + i);
            dl[i] = pd[ro * DI_];
            uu[i] = pu[ro * DI_];
            Bv[i] = pB[ro * DBCW];
            Cv[i] = pB[ro * DBCW + DS_];
            if (s == 0) zz[i] = pz[ro * (size_t)(2*DI_)];
        }
#pragma unroll
        for (int i = 0; i < SB; i++) {
            float e = __expf(dl[i] * Av);
            h = h * e + (dl[i] * uu[i]) * Bv[i];
            float p = h * Cv[i];
            p += __shfl_xor_sync(0xffffffffu, p, 1);
            p += __shfl_xor_sync(0xffffffffu, p, 2);
            p += __shfl_xor_sync(0xffffffffu, p, 4);
            p += __shfl_xor_sync(0xffffffffu, p, 8);
            if (s == 0) {
                float sg = zz[i] / (1.f + __expf(-zz[i]));
                py[(size_t)(t + i) * DI_] = __float2half((p + uu[i] * Dv) * sg);
            }
        }
    }
    for (; t < len; t++) {
        const size_t ro = (size_t)t;
        float dl = pd[ro * DI_], uu = pu[ro * DI_];
        float Bv = pB[ro * DBCW], Cv = pB[ro * DBCW + DS_];
        float e = __expf(dl * Av);
        h = h * e + (dl * uu) * Bv;
        float p = h * Cv;
        p += __shfl_xor_sync(0xffffffffu, p, 1);
        p += __shfl_xor_sync(0xffffffffu, p, 2);
        p += __shfl_xor_sync(0xffffffffu, p, 4);
        p += __shfl_xor_sync(0xffffffffu, p, 8);
        if (s == 0) {
            float z = pz[ro * (size_t)(2*DI_)];
            float sg = z / (1.f + __expf(-z));
            py[ro * DI_] = __float2half((p + uu * Dv) * sg);
        }
    }
}

// ---------------- masked mean, two phase (partials in g_delta) --------------
#define MEAN_SLICES 16
__global__ void mean1_kernel(float* __restrict__ partial)
{
    int b = blockIdx.y, slice = blockIdx.z;
    int o = blockIdx.x * blockDim.x + threadIdx.x;
    int len = g_len[b];
    if (len < 1) len = 1;
    int t0 = slice * (TLEN / MEAN_SLICES);
    int t1 = t0 + (TLEN / MEAN_SLICES);
    if (t1 > len) t1 = len;
    float sum = 0.f;
    const float* p = g_ob + ((size_t)b * TLEN + t0) * DO_ + o;
    int t = t0;
    for (; t + 4 <= t1; t += 4, p += 4 * DO_) {
        float v0 = p[0], v1 = p[DO_], v2 = p[2*DO_], v3 = p[3*DO_];
        sum += (v0 + v1) + (v2 + v3);
    }
    for (; t < t1; t++, p += DO_) sum += *p;
    partial[((size_t)b * MEAN_SLICES + slice) * DO_ + o] = sum;
}
__global__ void mean2_kernel(const float* __restrict__ partial,
                             float* __restrict__ out)
{
    int b = blockIdx.y;
    int o = blockIdx.x * blockDim.x + threadIdx.x;
    int len = g_len[b];
    if (len < 1) len = 1;
    float sum = 0.f;
#pragma unroll
    for (int i = 0; i < MEAN_SLICES; i++)
        sum += partial[((size_t)b * MEAN_SLICES + i) * DO_ + o];
    out[b * DO_ + o] = sum / (float)len;
}

static void launch_gemm(const __half* A, int lda, const __half* W, int ldb,
                        const float* bias, float* C, int ldc,
                        __half* hout, int hld,
                        int M, int N, int K, int flags)
{
    int nch = (K + 63) / 64;
    if (nch < 2) nch = 2;
    dim3 grid((N + 127) / 128, M / 128);
    gemm_mma<<<grid, 256, GTC_SMEM>>>(A, lda, W, ldb, bias, C, ldc,
                                      hout, hld, N, K, nch, flags);
}
static void conv_w(const float* W, __half* wh, size_t n) {
    convert_h<<<(unsigned)((n/4 + 255) / 256), 256>>>(W, wh, n/4);
}

extern "C" void kernel_launch(void* const* d_in, const int* in_sizes, int n_in,
                              void* d_out, int out_size)
{
    const float* features  = (const float*)d_in[0];
    const void*  mask      = d_in[1];
    const float* inp_w     = (const float*)d_in[2];
    const float* inp_b     = (const float*)d_in[3];
    const float* norm_w    = (const float*)d_in[4];
    const float* norm_b    = (const float*)d_in[5];
    const float* in_proj_w = (const float*)d_in[6];
    const float* conv_w_   = (const float*)d_in[7];
    const float* conv_b    = (const float*)d_in[8];
    const float* x_proj_w  = (const float*)d_in[9];
    const float* dt_proj_w = (const float*)d_in[10];
    const float* dt_proj_b = (const float*)d_in[11];
    const float* A_log     = (const float*)d_in[12];
    const float* Dskip     = (const float*)d_in[13];
    const float* mout_w    = (const float*)d_in[14];
    const float* out_w     = (const float*)d_in[15];
    const float* out_b     = (const float*)d_in[16];
    float* out = (float*)d_out;

    cudaFuncSetAttribute(gemm_mma, cudaFuncAttributeMaxDynamicSharedMemorySize, GTC_SMEM);

    float *px, *pxz, *pu, *pdbc, *pdelta, *pob;
    __half *pah, *pwh, *pdh;
    cudaGetSymbolAddress((void**)&px,     g_x);
    cudaGetSymbolAddress((void**)&pxz,    g_xz);
    cudaGetSymbolAddress((void**)&pu,     g_u);
    cudaGetSymbolAddress((void**)&pdbc,   g_dbc);
    cudaGetSymbolAddress((void**)&pdelta, g_delta);
    cudaGetSymbolAddress((void**)&pob,    g_ob);
    cudaGetSymbolAddress((void**)&pah,    g_ah);
    cudaGetSymbolAddress((void**)&pwh,    g_wh);
    cudaGetSymbolAddress((void**)&pdh,    g_dh);

    detect_mask_kernel<<<1, 256>>>((const unsigned char*)mask);

    // x = features @ inp_w^T + inp_b   (masked tiles skipped)
    convert_h<<<(unsigned)(((size_t)MROWS*DIN_/4 + 255)/256), 256>>>(
        features, pah, (size_t)MROWS*DIN_/4);
    conv_w(inp_w, pwh, (size_t)DM_*DIN_);
    launch_gemm(pah, DIN_, pwh, DIN_, inp_b, px, DM_, nullptr, 0,
                MROWS, DM_, DIN_, 4);

    for (int l = 0; l < LNUM; l++) {
        // xn (fp16 direct, masked rows skipped)
        layernorm_h_kernel<<<MROWS, 256>>>(px, norm_w + l*DM_, norm_b + l*DM_, pah);

        // xz = xn @ in_proj_w^T
        conv_w(in_proj_w + (size_t)l*2*DI_*DM_, pwh, (size_t)2*DI_*DM_);
        launch_gemm(pah, DM_, pwh, DM_, nullptr, pxz, 2*DI_, nullptr, 0,
                    MROWS, 2*DI_, DM_, 4);

        // u = silu(conv(xi)+b): fp32 + fp16 dual write, masked rows skipped
        conv_silu_kernel<<<(unsigned)((MROWS*(size_t)DI_)/256), 256>>>(
            conv_w_ + (size_t)l*DI_*DC_, conv_b + l*DI_);

        // dbc = u @ x_proj_w^T  (fp32 + fp16 dual write)
        conv_w(x_proj_w + (size_t)l*DBCW*DI_, pwh, (size_t)DBCW*DI_);
        launch_gemm(pah, DI_, pwh, DI_, nullptr, pdbc, DBCW, pdh, DBCW,
                    MROWS, DBCW, DI_, 4);

        // delta = softplus(dt @ dt_proj_w^T + dt_proj_b)
        conv_w(dt_proj_w + (size_t)l*DI_*DTR_, pwh, (size_t)DI_*DTR_);
        launch_gemm(pdh, DBCW, pwh, DTR_, dt_proj_b + l*DI_, pdelta, DI_,
                    nullptr, 0, MROWS, DI_, DTR_, 2 | 4);

        // selective scan + fused gate, batched loads (SB=4), tail skipped
        scan_kernel<<<512, 256>>>(A_log + (size_t)l*DI_*DS_, Dskip + l*DI_);

        // x += y_gated @ mout_w^T
        conv_w(mout_w + (size_t)l*DM_*DI_, pwh, (size_t)DM_*DI_);
        launch_gemm(pah, DI_, pwh, DI_, nullptr, px, DM_, nullptr, 0,
                    MROWS, DM_, DI_, 1 | 4);
    }

    // ob = x @ out_w^T + out_b
    convert_h<<<(unsigned)(((size_t)MROWS*DM_/4 + 255)/256), 256>>>(
        px, pah, (size_t)MROWS*DM_/4);
    conv_w(out_w, pwh, (size_t)DO_*DM_);
    launch_gemm(pah, DM_, pwh, DM_, out_b, pob, DO_, nullptr, 0,
                MROWS, DO_, DM_, 4);

    // masked mean, two-phase (partials into g_delta — free at this point)
    mean1_kernel<<<dim3(DO_/256, BSZ, MEAN_SLICES), 256>>>(pdelta);
    mean2_kernel<<<dim3(DO_/256, BSZ), 256>>>(pdelta, out);
}